// round 4
// baseline (speedup 1.0000x reference)
#include <cuda_runtime.h>
#include <cstdint>

// SpatialCNN: 4 directional scans, step: out[p] += relu(conv1d_C2C(out[p_prev]))
// x (B=64, C=128, H=36, W=100), w (C, C, KS=9), fp32, in-place in d_out.
// Each step = GEMM M=128(co) x K=1152(ci*9) x N=B*L.
// This version: packed fp32x2 FMA (fma.rn.f32x2) with M-paired accumulators,
// pre-broadcast (v,v) window pairs in smem, cp.async weight double-buffering.

#define B_ 64
#define C_ 128
#define H_ 36
#define W_ 100
#define KS_ 9
#define CH_STRIDE (H_ * W_)          // 3600
#define B_STRIDE  (C_ * H_ * W_)     // 460800
#define KTOT (C_ * KS_)              // 1152

typedef unsigned long long u64;

__device__ __forceinline__ u64 pack2(float lo, float hi) {
    u64 r; asm("mov.b64 %0, {%1, %2};" : "=l"(r) : "f"(lo), "f"(hi)); return r;
}
__device__ __forceinline__ void unpack2(float& lo, float& hi, u64 v) {
    asm("mov.b64 {%0, %1}, %2;" : "=f"(lo), "=f"(hi) : "l"(v));
}
__device__ __forceinline__ void ffma2(u64& d, u64 a, u64 b) {
    asm("fma.rn.f32x2 %0, %1, %2, %0;" : "+l"(d) : "l"(a), "l"(b));
}
__device__ __forceinline__ void cp_async16(uint32_t dst, const void* src) {
    asm volatile("cp.async.cg.shared.global [%0], [%1], 16;" :: "r"(dst), "l"(src));
}
__device__ __forceinline__ void cp_commit() {
    asm volatile("cp.async.commit_group;");
}
__device__ __forceinline__ void cp_wait_all() {
    asm volatile("cp.async.wait_group 0;");
}

// Transposed weights: [dir][(ci*KS + k)*C + co]
__device__ float g_wT[4][KTOT * C_];

__global__ void transpose_weights_kernel(const float* __restrict__ wd,
                                         const float* __restrict__ wu,
                                         const float* __restrict__ wr,
                                         const float* __restrict__ wl) {
    int idx = blockIdx.x * blockDim.x + threadIdx.x;
    const int total = C_ * C_ * KS_;
    if (idx >= total) return;
    int co  = idx / (C_ * KS_);
    int rem = idx % (C_ * KS_);      // ci*KS + k
    g_wT[0][rem * C_ + co] = wd[idx];
    g_wT[1][rem * C_ + co] = wu[idx];
    g_wT[2][rem * C_ + co] = wr[idx];
    g_wT[3][rem * C_ + co] = wl[idx];
}

// One scan step as a register-blocked GEMM with f32x2 packed math.
//   MT x NT : block tile (co x line positions). Micro: 2 co (one f32x2 pair) x NN lines.
//   L       : conv line length, ES: element stride along line, NTILES: n-tiles.
// Block = (MT/2)*(NT/NN) threads. Grid: ((C_/MT)*NTILES, B_).
template <int MT, int NT, int NN, int L, int ES, int NTILES>
__global__ void __launch_bounds__((MT / 2) * (NT / NN), 1)
gemm_step(float* __restrict__ out, int dir, int prevOff, int curOff) {
    constexpr int THREADS = (MT / 2) * (NT / NN);
    constexpr int NTHR_N  = NT / NN;
    constexpr int WIN     = NT + KS_ - 1;
    constexpr int CI_CH   = 16;
    constexpr int KKC     = CI_CH * KS_;        // 144 rows per A chunk
    constexpr int NCH     = C_ / CI_CH;         // 8 chunks
    constexpr int CHUNK4  = KKC * MT / 4;       // float4s per A chunk
    constexpr int NLD     = (CHUNK4 + THREADS - 1) / THREADS;

    extern __shared__ float smem[];
    float* sA   = smem;                          // 2 * KKC * MT floats (dbl-buffered W)
    u64*   sPbb = (u64*)(smem + 2 * KKC * MT);   // C_ * WIN  (v,v) pairs

    const int b     = blockIdx.y;
    const int ntile = blockIdx.x % NTILES;
    const int mo    = (blockIdx.x / NTILES) * MT;
    const int tid   = threadIdx.x;
    const int tn    = tid % NTHR_N;
    const int tm    = tid / NTHR_N;
    const int n0    = tn * NN;
    const int co0   = tm * 2;

    const float* __restrict__ wT = g_wT[dir];

    // Prefetch A chunk 0 via cp.async (overlaps the prev-window staging below).
    {
        uint32_t sA0 = (uint32_t)__cvta_generic_to_shared(sA);
        const float* __restrict__ gA = wT + mo;
#pragma unroll
        for (int j = 0; j < NLD; j++) {
            int idx = tid + j * THREADS;
            if (idx < CHUNK4) {
                int r = idx / (MT / 4), cc = idx % (MT / 4);
                cp_async16(sA0 + idx * 16, gA + r * C_ + cc * 4);
            }
        }
        cp_commit();
    }

    // Stage prev window (all channels + halo) as pre-broadcast (v,v) pairs.
    {
        const float* __restrict__ prevBase = out + (size_t)b * B_STRIDE + prevOff;
        const int lineBase = ntile * NT - KS_ / 2;
        for (int i = tid; i < C_ * WIN; i += THREADS) {
            int ci = i / WIN, j = i % WIN;
            int line = lineBase + j;
            float v = 0.0f;
            if (line >= 0 && line < L)
                v = prevBase[ci * CH_STRIDE + line * ES];
            sPbb[i] = pack2(v, v);
        }
    }
    cp_wait_all();
    __syncthreads();

    u64 acc2[NN];
#pragma unroll
    for (int n = 0; n < NN; n++) acc2[n] = 0ull;

    for (int c = 0; c < NCH; c++) {
        // Prefetch next chunk into the other buffer while computing this one.
        if (c + 1 < NCH) {
            uint32_t sAn = (uint32_t)__cvta_generic_to_shared(sA + ((c + 1) & 1) * (KKC * MT));
            const float* __restrict__ gA = wT + (c + 1) * KKC * C_ + mo;
#pragma unroll
            for (int j = 0; j < NLD; j++) {
                int idx = tid + j * THREADS;
                if (idx < CHUNK4) {
                    int r = idx / (MT / 4), cc = idx % (MT / 4);
                    cp_async16(sAn + idx * 16, gA + r * C_ + cc * 4);
                }
            }
            cp_commit();
        }

        const float* __restrict__ sAc = sA + (c & 1) * (KKC * MT);
#pragma unroll 1
        for (int cl = 0; cl < CI_CH; cl++) {
            const int ci = c * CI_CH + cl;
            // Window pairs for this ci: NN+8 LDS.64, already broadcast-packed.
            u64 wbb[NN + KS_ - 1];
            const u64* __restrict__ wp = sPbb + ci * WIN + n0;
#pragma unroll
            for (int j = 0; j < NN + KS_ - 1; j++) wbb[j] = wp[j];

            const u64* __restrict__ ap64 =
                (const u64*)(sAc + cl * (KS_ * MT) + co0);
#pragma unroll
            for (int k = 0; k < KS_; k++) {
                u64 a2 = ap64[k * (MT / 2)];     // (w[co0], w[co0+1])
#pragma unroll
                for (int n = 0; n < NN; n++)
                    ffma2(acc2[n], a2, wbb[n + k]);
            }
        }

        cp_wait_all();
        __syncthreads();
    }

    // Epilogue: out[cur] += relu(acc). NT divides the line -> no guards.
    float* __restrict__ curBase = out + (size_t)b * B_STRIDE + curOff;
#pragma unroll
    for (int n = 0; n < NN; n++) {
        float v0, v1;
        unpack2(v0, v1, acc2[n]);
        const int line = ntile * NT + n0 + n;
        float* p0 = curBase + (mo + co0) * CH_STRIDE + line * ES;
        float* p1 = p0 + CH_STRIDE;
        *p0 = *p0 + fmaxf(v0, 0.0f);
        *p1 = *p1 + fmaxf(v1, 0.0f);
    }
}

// H-steps: MT=128, NT=50, NN=5 -> 640 thr (20 warps, SMSP-balanced), grid 2x64.
#define SMEM_H ((2 * 144 * 128) * 4 + (128 * (50 + 8)) * 8)
// W-steps: MT=64, NT=36, NN=3 -> 384 thr (12 warps), grid 2x64 (2 m-tiles).
#define SMEM_W ((2 * 144 * 64) * 4 + (128 * (36 + 8)) * 8)

extern "C" void kernel_launch(void* const* d_in, const int* in_sizes, int n_in,
                              void* d_out, int out_size) {
    const float* x = (const float*)d_in[0];
    float* out = (float*)d_out;
    (void)in_sizes; (void)n_in; (void)out_size;

    cudaFuncSetAttribute((const void*)gemm_step<128, 50, 5, W_, 1, 2>,
                         cudaFuncAttributeMaxDynamicSharedMemorySize, SMEM_H);
    cudaFuncSetAttribute((const void*)gemm_step<64, 36, 3, H_, W_, 1>,
                         cudaFuncAttributeMaxDynamicSharedMemorySize, SMEM_W);

    // out = x (all scans run in-place, accumulating)
    cudaMemcpyAsync(out, x, (size_t)B_ * C_ * H_ * W_ * sizeof(float),
                    cudaMemcpyDeviceToDevice, 0);

    transpose_weights_kernel<<<(C_ * C_ * KS_ + 255) / 256, 256>>>(
        (const float*)d_in[1], (const float*)d_in[2],
        (const float*)d_in[3], (const float*)d_in[4]);

    const dim3 gridH(2, B_);   // 2 n-tiles of 50, 1 m-tile of 128
    const dim3 gridW(2, B_);   // 2 m-tiles of 64, 1 n-tile of 36

    // Scan 1: down (axis H, forward), w_d
    for (int h = 1; h < H_; h++)
        gemm_step<128, 50, 5, W_, 1, 2><<<gridH, 640, SMEM_H>>>(out, 0, (h - 1) * W_, h * W_);

    // Scan 2: up (axis H, reverse), w_u
    for (int h = H_ - 2; h >= 0; h--)
        gemm_step<128, 50, 5, W_, 1, 2><<<gridH, 640, SMEM_H>>>(out, 1, (h + 1) * W_, h * W_);

    // Scan 3: right (axis W, forward), w_r
    for (int w = 1; w < W_; w++)
        gemm_step<64, 36, 3, H_, W_, 1><<<gridW, 384, SMEM_W>>>(out, 2, w - 1, w);

    // Scan 4: left (axis W, reverse), w_l
    for (int w = W_ - 2; w >= 0; w--)
        gemm_step<64, 36, 3, H_, W_, 1><<<gridW, 384, SMEM_W>>>(out, 3, w + 1, w);
}

// round 5
// speedup vs baseline: 1.6526x; 1.6526x over previous
#include <cuda_runtime.h>
#include <cuda_bf16.h>
#include <cstdint>

// SpatialCNN: 4 directional scans; step: out[p] += relu(conv1d_C2C(out[p_prev]))
// x (B=64, C=128, H=36, W=100), w (C, C, KS=9), fp32, in-place in d_out.
// Tensor-core version: bf16 hi/lo split (3-MMA scheme) with mma.sync.m16n8k16,
// fp32 accumulate. GEMM per step: out^T[n,co] += sum_{s,ci} X[ci,n+s-4] W[co,ci,s].
//   A = X^T (m=line, k=ci)  from smem via ldmatrix (272B rows, conflict-free)
//   B = W_s^T (k=ci, n=co)  prepacked in gmem in exact fragment order (LDG.128)

#define B_ 64
#define C_ 128
#define H_ 36
#define W_ 100
#define KS_ 9
#define CH_STRIDE (H_ * W_)          // 3600
#define B_STRIDE  (C_ * H_ * W_)     // 460800

#define ROWB 272                     // smem row bytes: 128 bf16 (256B) + 16B pad
#define ROWE 136                     // row stride in bf16 elems

// Prepacked weights: frag = ((dir*9+s)*8 + cif)*16 + co8 ; [frag][lane] = uint4
// uint4 = { b0hi, b1hi, b0lo, b1lo } for mma B-fragment of (k=ci tile 16, n=co tile 8)
__device__ uint4 g_wPack[4 * 9 * 8 * 16 * 32];

__device__ __forceinline__ uint32_t pk_hi(float a, float b) {
    __nv_bfloat16 ha = __float2bfloat16(a), hb = __float2bfloat16(b);
    return (uint32_t)__bfloat16_as_ushort(ha) |
           ((uint32_t)__bfloat16_as_ushort(hb) << 16);
}
__device__ __forceinline__ float bf_res(float v) {     // v - bf16(v)
    return v - __bfloat162float(__float2bfloat16(v));
}

__global__ void prepack_kernel(const float* __restrict__ wd,
                               const float* __restrict__ wu,
                               const float* __restrict__ wr,
                               const float* __restrict__ wl) {
    int idx = blockIdx.x * 256 + threadIdx.x;
    const int total = 4 * 9 * 8 * 16 * 32;
    if (idx >= total) return;
    int lane = idx & 31;
    int fr   = idx >> 5;
    int co8  = fr & 15;
    int cif  = (fr >> 4) & 7;
    int rem  = fr >> 7;              // dir*9 + s
    int s    = rem % 9;
    int dir  = rem / 9;
    const float* w = (dir == 0) ? wd : (dir == 1) ? wu : (dir == 2) ? wr : wl;

    int co = co8 * 8 + (lane >> 2);
    int ci = cif * 16 + (lane & 3) * 2;
    float v00 = w[(co * C_ + ci    ) * KS_ + s];
    float v01 = w[(co * C_ + ci + 1) * KS_ + s];
    float v10 = w[(co * C_ + ci + 8) * KS_ + s];
    float v11 = w[(co * C_ + ci + 9) * KS_ + s];

    uint4 r;
    r.x = pk_hi(v00, v01);
    r.y = pk_hi(v10, v11);
    r.z = pk_hi(bf_res(v00), bf_res(v01));
    r.w = pk_hi(bf_res(v10), bf_res(v11));
    g_wPack[idx] = r;
}

__device__ __forceinline__ void ldsm4(uint32_t a[4], uint32_t addr) {
    asm volatile("ldmatrix.sync.aligned.m8n8.x4.shared.b16 {%0,%1,%2,%3}, [%4];"
                 : "=r"(a[0]), "=r"(a[1]), "=r"(a[2]), "=r"(a[3]) : "r"(addr));
}
__device__ __forceinline__ void mma16816(float c[4], const uint32_t a[4],
                                         uint32_t b0, uint32_t b1) {
    asm volatile(
        "mma.sync.aligned.m16n8k16.row.col.f32.bf16.bf16.f32 "
        "{%0,%1,%2,%3},{%4,%5,%6,%7},{%8,%9},{%0,%1,%2,%3};"
        : "+f"(c[0]), "+f"(c[1]), "+f"(c[2]), "+f"(c[3])
        : "r"(a[0]), "r"(a[1]), "r"(a[2]), "r"(a[3]), "r"(b0), "r"(b1));
}

// MF  : m16-fragments along the line dim (4 for H-steps, 3 for W-steps)
// COF : co8-fragments per warp (2 -> block covers 128 co; 1 -> 64 co, co-split grid)
// WINR: smem window rows (MF*16 + 8), L: line length, ES: element stride along line
template <int MF, int COF, int WINR, int L, int ES>
__global__ void __launch_bounds__(256, 1)
mma_step(float* __restrict__ out, int dir, int prevOff, int curOff) {
    extern __shared__ unsigned short smem_u16[];
    unsigned short* sHi = smem_u16;                 // [WINR][ROWE]
    unsigned short* sLo = smem_u16 + WINR * ROWE;

    const int tid  = threadIdx.x;
    const int lane = tid & 31;
    const int warp = tid >> 5;
    const int b    = blockIdx.y;

    int n0, co8base;
    if (COF == 2) { n0 = blockIdx.x * 64; co8base = warp * 2; }
    else          { n0 = 0;               co8base = blockIdx.x * 8 + warp; }

    // ---- Stage prev window: fp32 -> bf16 hi/lo split ----
    {
        const float* __restrict__ prevBase = out + (size_t)b * B_STRIDE + prevOff;
        for (int i = tid; i < C_ * WINR; i += 256) {
            int ci = i / WINR, j = i - ci * WINR;
            int line = n0 - 4 + j;
            float v = 0.0f;
            if (line >= 0 && line < L)
                v = prevBase[ci * CH_STRIDE + line * ES];
            __nv_bfloat16 h = __float2bfloat16(v);
            float r = v - __bfloat162float(h);
            sHi[j * ROWE + ci] = __bfloat16_as_ushort(h);
            sLo[j * ROWE + ci] = __bfloat16_as_ushort(__float2bfloat16(r));
        }
    }
    __syncthreads();

    const uint32_t shBase = (uint32_t)__cvta_generic_to_shared(sHi);
    const uint32_t slBase = (uint32_t)__cvta_generic_to_shared(sLo);
    const uint32_t aOff   = (uint32_t)(lane & 15) * ROWB + ((lane >> 4) & 1) * 16;

    float acc[MF][COF][4];
#pragma unroll
    for (int mf = 0; mf < MF; mf++)
#pragma unroll
        for (int f = 0; f < COF; f++)
#pragma unroll
            for (int q = 0; q < 4; q++) acc[mf][f][q] = 0.0f;

    const uint4* __restrict__ wp = g_wPack;
    const int dbase = dir * 72;   // (dir*9+s)*8+cif == dir*72 + s*8+cif

    uint4 Bc[COF];
#pragma unroll
    for (int f = 0; f < COF; f++)
        Bc[f] = wp[((dbase + 0) * 16 + co8base + f) * 32 + lane];

#pragma unroll 1
    for (int s = 0; s < 9; s++) {
#pragma unroll
        for (int cif = 0; cif < 8; cif++) {
            uint4 Bn[COF];
            int nidx = s * 8 + cif + 1;
            if (nidx < 72) {
#pragma unroll
                for (int f = 0; f < COF; f++)
                    Bn[f] = wp[((dbase + nidx) * 16 + co8base + f) * 32 + lane];
            } else {
#pragma unroll
                for (int f = 0; f < COF; f++) Bn[f] = Bc[f];
            }

            uint32_t ah[MF][4], al[MF][4];
#pragma unroll
            for (int mf = 0; mf < MF; mf++) {
                uint32_t off = aOff + (uint32_t)s * ROWB + mf * (16 * ROWB) + cif * 32;
                ldsm4(ah[mf], shBase + off);
                ldsm4(al[mf], slBase + off);
            }
#pragma unroll
            for (int mf = 0; mf < MF; mf++)
#pragma unroll
                for (int f = 0; f < COF; f++) {
                    mma16816(acc[mf][f], ah[mf], Bc[f].x, Bc[f].y);  // hi*hi
                    mma16816(acc[mf][f], ah[mf], Bc[f].z, Bc[f].w);  // hi*wlo
                    mma16816(acc[mf][f], al[mf], Bc[f].x, Bc[f].y);  // xlo*hi
                }
#pragma unroll
            for (int f = 0; f < COF; f++) Bc[f] = Bn[f];
        }
    }

    // ---- Epilogue: out[cur] += relu(acc), guarded ----
    float* __restrict__ curBase = out + (size_t)b * B_STRIDE + curOff;
    const int r0 = lane >> 2;            // 0..7
    const int c0 = (lane & 3) * 2;
#pragma unroll
    for (int mf = 0; mf < MF; mf++) {
        const int l0 = n0 + mf * 16 + r0;
        const int l1 = l0 + 8;
#pragma unroll
        for (int f = 0; f < COF; f++) {
            const int co = (co8base + f) * 8 + c0;
            float* pc = curBase + (size_t)co * CH_STRIDE;
            if (l0 < L) {
                float* p = pc + l0 * ES;
                p[0]         += fmaxf(acc[mf][f][0], 0.0f);
                p[CH_STRIDE] += fmaxf(acc[mf][f][1], 0.0f);
            }
            if (l1 < L) {
                float* p = pc + l1 * ES;
                p[0]         += fmaxf(acc[mf][f][2], 0.0f);
                p[CH_STRIDE] += fmaxf(acc[mf][f][3], 0.0f);
            }
        }
    }
}

#define WINR_H 72   // MF=4: rows 0..63, +s(8) => 72
#define WINR_W 56   // MF=3: rows 0..47, +s(8) => 56
#define SMEM_H (2 * WINR_H * ROWB)   // 39168 B
#define SMEM_W (2 * WINR_W * ROWB)   // 30464 B

extern "C" void kernel_launch(void* const* d_in, const int* in_sizes, int n_in,
                              void* d_out, int out_size) {
    const float* x = (const float*)d_in[0];
    float* out = (float*)d_out;
    (void)in_sizes; (void)n_in; (void)out_size;

    // out = x (all scans accumulate in place)
    cudaMemcpyAsync(out, x, (size_t)B_ * C_ * H_ * W_ * sizeof(float),
                    cudaMemcpyDeviceToDevice, 0);

    // Pre-split + fragment-pack all weights (L2-resident, 2.36MB)
    prepack_kernel<<<(4 * 9 * 8 * 16 * 32 + 255) / 256, 256>>>(
        (const float*)d_in[1], (const float*)d_in[2],
        (const float*)d_in[3], (const float*)d_in[4]);

    // H-steps: lines along W (L=100, ES=1). grid = (2 n-tiles of 64 rows, 64 b).
    const dim3 gridH(2, B_);
    // W-steps: lines along H (L=36, ES=W). grid = (2 co-halves, 64 b).
    const dim3 gridW(2, B_);

    // Scan 1: down (axis H, forward), w_d (dir 0)
    for (int h = 1; h < H_; h++)
        mma_step<4, 2, WINR_H, W_, 1><<<gridH, 256, SMEM_H>>>(out, 0, (h - 1) * W_, h * W_);

    // Scan 2: up (axis H, reverse), w_u (dir 1)
    for (int h = H_ - 2; h >= 0; h--)
        mma_step<4, 2, WINR_H, W_, 1><<<gridH, 256, SMEM_H>>>(out, 1, (h + 1) * W_, h * W_);

    // Scan 3: right (axis W, forward), w_r (dir 2)
    for (int w = 1; w < W_; w++)
        mma_step<3, 1, WINR_W, H_, W_><<<gridW, 256, SMEM_W>>>(out, 2, w - 1, w);

    // Scan 4: left (axis W, reverse), w_l (dir 3)
    for (int w = W_ - 2; w >= 0; w--)
        mma_step<3, 1, WINR_W, H_, W_><<<gridW, 256, SMEM_W>>>(out, 3, w + 1, w);
}

// round 6
// speedup vs baseline: 2.1752x; 1.3162x over previous
#include <cuda_runtime.h>
#include <cuda_bf16.h>
#include <cstdint>

// SpatialCNN: 4 directional scans; step: out[p] += relu(conv1d_C2C(out[p_prev]))
// x (B=64, C=128, H=36, W=100), w (C, C, KS=9), fp32, in-place in d_out.
// bf16 hi/lo split (3-MMA) with mma.sync.m16n8k16, fp32 accumulate.
// Warp grid re-shaped: line-groups x co-groups so each warp loads FEW A-frags
// (ldsm) and reuses them across MANY co-fragments (COF B-frags from L2).

#define B_ 64
#define C_ 128
#define H_ 36
#define W_ 100
#define KS_ 9
#define CH_STRIDE (H_ * W_)          // 3600
#define B_STRIDE  (C_ * H_ * W_)     // 460800

#define ROWB 272                     // smem row bytes: 128 bf16 + 16B pad
#define ROWE 136                     // row stride in bf16 elems

// Prepacked weights: [((dir*9+s)*8 + cif)*16 + co8][lane] = uint4
// uint4 = { b0hi, b1hi, b0lo, b1lo } : mma B-fragment (k=16 ci, n=8 co)
__device__ uint4 g_wPack[4 * 9 * 8 * 16 * 32];

__device__ __forceinline__ uint32_t pk_hi(float a, float b) {
    __nv_bfloat16 ha = __float2bfloat16(a), hb = __float2bfloat16(b);
    return (uint32_t)__bfloat16_as_ushort(ha) |
           ((uint32_t)__bfloat16_as_ushort(hb) << 16);
}
__device__ __forceinline__ float bf_res(float v) {     // v - bf16(v)
    return v - __bfloat162float(__float2bfloat16(v));
}

__global__ void prepack_kernel(const float* __restrict__ wd,
                               const float* __restrict__ wu,
                               const float* __restrict__ wr,
                               const float* __restrict__ wl) {
    int idx = blockIdx.x * 256 + threadIdx.x;
    const int total = 4 * 9 * 8 * 16 * 32;
    if (idx >= total) return;
    int lane = idx & 31;
    int fr   = idx >> 5;
    int co8  = fr & 15;
    int cif  = (fr >> 4) & 7;
    int rem  = fr >> 7;              // dir*9 + s
    int s    = rem % 9;
    int dir  = rem / 9;
    const float* w = (dir == 0) ? wd : (dir == 1) ? wu : (dir == 2) ? wr : wl;

    int co = co8 * 8 + (lane >> 2);
    int ci = cif * 16 + (lane & 3) * 2;
    float v00 = w[(co * C_ + ci    ) * KS_ + s];
    float v01 = w[(co * C_ + ci + 1) * KS_ + s];
    float v10 = w[(co * C_ + ci + 8) * KS_ + s];
    float v11 = w[(co * C_ + ci + 9) * KS_ + s];

    uint4 r;
    r.x = pk_hi(v00, v01);
    r.y = pk_hi(v10, v11);
    r.z = pk_hi(bf_res(v00), bf_res(v01));
    r.w = pk_hi(bf_res(v10), bf_res(v11));
    g_wPack[idx] = r;
}

__device__ __forceinline__ void ldsm4(uint32_t a[4], uint32_t addr) {
    asm volatile("ldmatrix.sync.aligned.m8n8.x4.shared.b16 {%0,%1,%2,%3}, [%4];"
                 : "=r"(a[0]), "=r"(a[1]), "=r"(a[2]), "=r"(a[3]) : "r"(addr));
}
__device__ __forceinline__ void mma16816(float c[4], const uint32_t a[4],
                                         uint32_t b0, uint32_t b1) {
    asm volatile(
        "mma.sync.aligned.m16n8k16.row.col.f32.bf16.bf16.f32 "
        "{%0,%1,%2,%3},{%4,%5,%6,%7},{%8,%9},{%0,%1,%2,%3};"
        : "+f"(c[0]), "+f"(c[1]), "+f"(c[2]), "+f"(c[3])
        : "r"(a[0]), "r"(a[1]), "r"(a[2]), "r"(a[3]), "r"(b0), "r"(b1));
}

// One warp's share of a step-GEMM: MF m16-frags (lines) x COF co8-frags.
template <int MF, int COF, int L, int ES>
__device__ __forceinline__ void warp_work(
    const unsigned short* sHi, const unsigned short* sLo,
    int rowbase, int co8base, int lane, int dir,
    float* __restrict__ curBase, int line0)
{
    const uint32_t aOff = (uint32_t)(lane & 15) * ROWB + ((lane >> 4) & 1) * 16
                        + (uint32_t)rowbase * ROWB;
    const uint32_t shBase = (uint32_t)__cvta_generic_to_shared(sHi) + aOff;
    const uint32_t slBase = (uint32_t)__cvta_generic_to_shared(sLo) + aOff;

    float acc[MF][COF][4];
#pragma unroll
    for (int mf = 0; mf < MF; mf++)
#pragma unroll
        for (int f = 0; f < COF; f++)
#pragma unroll
            for (int q = 0; q < 4; q++) acc[mf][f][q] = 0.0f;

    const uint4* __restrict__ wp = g_wPack;
    const int dbase = dir * 72;

    uint4 Bc[COF], Bn[COF];
#pragma unroll
    for (int f = 0; f < COF; f++)
        Bc[f] = wp[(dbase * 16 + co8base + f) * 32 + lane];

#pragma unroll 1
    for (int s = 0; s < 9; s++) {
#pragma unroll
        for (int cif = 0; cif < 8; cif++) {
            const int idx  = s * 8 + cif;
            const int nidx = (idx + 1 < 72) ? idx + 1 : idx;
#pragma unroll
            for (int f = 0; f < COF; f++)
                Bn[f] = wp[((dbase + nidx) * 16 + co8base + f) * 32 + lane];

            uint32_t ah[MF][4], al[MF][4];
#pragma unroll
            for (int mf = 0; mf < MF; mf++) {
                uint32_t off = (uint32_t)(s + mf * 16) * ROWB + cif * 32;
                ldsm4(ah[mf], shBase + off);
                ldsm4(al[mf], slBase + off);
            }
#pragma unroll
            for (int mf = 0; mf < MF; mf++)
#pragma unroll
                for (int f = 0; f < COF; f++) {
                    mma16816(acc[mf][f], ah[mf], Bc[f].x, Bc[f].y);  // hi*Whi
                    mma16816(acc[mf][f], ah[mf], Bc[f].z, Bc[f].w);  // hi*Wlo
                    mma16816(acc[mf][f], al[mf], Bc[f].x, Bc[f].y);  // lo*Whi
                }
#pragma unroll
            for (int f = 0; f < COF; f++) Bc[f] = Bn[f];
        }
    }

    // Epilogue: out[cur] += relu(acc), guarded on line < L.
    const int r0 = lane >> 2;
    const int c0 = (lane & 3) * 2;
#pragma unroll
    for (int mf = 0; mf < MF; mf++) {
        const int l0 = line0 + mf * 16 + r0;
        const int l1 = l0 + 8;
#pragma unroll
        for (int f = 0; f < COF; f++) {
            const int co = (co8base + f) * 8 + c0;
            float* pc = curBase + (size_t)co * CH_STRIDE;
            if (l0 < L) {
                float* p = pc + l0 * ES;
                p[0]         += fmaxf(acc[mf][f][0], 0.0f);
                p[CH_STRIDE] += fmaxf(acc[mf][f][1], 0.0f);
            }
            if (l1 < L) {
                float* p = pc + l1 * ES;
                p[0]         += fmaxf(acc[mf][f][2], 0.0f);
                p[CH_STRIDE] += fmaxf(acc[mf][f][3], 0.0f);
            }
        }
    }
}

// Shared staging: prev slab fp32 -> bf16 hi/lo split into [WINR][ROWE] smem.
template <int WINR, int L, int ES, int THREADS>
__device__ __forceinline__ void stage_window(
    unsigned short* sHi, unsigned short* sLo,
    const float* __restrict__ prevBase, int n0, int tid)
{
    for (int i = tid; i < C_ * WINR; i += THREADS) {
        int ci = i / WINR, j = i - ci * WINR;
        int line = n0 - 4 + j;
        float v = 0.0f;
        if (line >= 0 && line < L)
            v = prevBase[ci * CH_STRIDE + line * ES];
        __nv_bfloat16 h = __float2bfloat16(v);
        float r = v - __bfloat162float(h);
        sHi[j * ROWE + ci] = __bfloat16_as_ushort(h);
        sLo[j * ROWE + ci] = __bfloat16_as_ushort(__float2bfloat16(r));
    }
}

// H-step: 512 thr = 16 warps (4 line-groups x 4 co-groups). MF=1, COF=4.
// Block: 64 lines x 128 co. Grid (2 n-tiles, B).
#define WINR_H 72
#define SMEM_H (2 * WINR_H * ROWB)
__global__ void __launch_bounds__(512, 1)
mma_step_h(float* __restrict__ out, int dir, int prevOff, int curOff) {
    extern __shared__ unsigned short smem_u16[];
    unsigned short* sHi = smem_u16;
    unsigned short* sLo = smem_u16 + WINR_H * ROWE;

    const int tid  = threadIdx.x;
    const int lane = tid & 31;
    const int warp = tid >> 5;
    const int b    = blockIdx.y;
    const int n0   = blockIdx.x * 64;

    stage_window<WINR_H, W_, 1, 512>(sHi, sLo,
        out + (size_t)b * B_STRIDE + prevOff, n0, tid);
    __syncthreads();

    const int lg = warp >> 2;             // 0..3 : 16-line group
    const int cg = warp & 3;              // 0..3 : 4 co8 frags
    const int line0 = n0 + lg * 16;
    if (line0 >= W_) return;              // dead tail group (tile 1), no barriers after

    warp_work<1, 4, W_, 1>(sHi, sLo, lg * 16, cg * 4, lane, dir,
                           out + (size_t)b * B_STRIDE + curOff, line0);
}

// W-step: 256 thr = 8 warps (2 line-groups x 4 co-groups), co-half per blockIdx.x.
// lg0: MF=2 (lines 0-31), lg1: MF=1 (lines 32-47, 4 valid). COF=2 (16 co).
#define WINR_W 56
#define SMEM_W (2 * WINR_W * ROWB)
__global__ void __launch_bounds__(256, 1)
mma_step_w(float* __restrict__ out, int dir, int prevOff, int curOff) {
    extern __shared__ unsigned short smem_u16[];
    unsigned short* sHi = smem_u16;
    unsigned short* sLo = smem_u16 + WINR_W * ROWE;

    const int tid  = threadIdx.x;
    const int lane = tid & 31;
    const int warp = tid >> 5;
    const int b    = blockIdx.y;

    stage_window<WINR_W, H_, W_, 256>(sHi, sLo,
        out + (size_t)b * B_STRIDE + prevOff, 0, tid);
    __syncthreads();

    const int lg = warp >> 2;             // 0,1
    const int cg = warp & 3;
    const int co8base = blockIdx.x * 8 + cg * 2;
    float* curBase = out + (size_t)b * B_STRIDE + curOff;

    if (lg == 0)
        warp_work<2, 2, H_, W_>(sHi, sLo, 0, co8base, lane, dir, curBase, 0);
    else
        warp_work<1, 2, H_, W_>(sHi, sLo, 32, co8base, lane, dir, curBase, 32);
}

extern "C" void kernel_launch(void* const* d_in, const int* in_sizes, int n_in,
                              void* d_out, int out_size) {
    const float* x = (const float*)d_in[0];
    float* out = (float*)d_out;
    (void)in_sizes; (void)n_in; (void)out_size;

    // out = x (all scans accumulate in place)
    cudaMemcpyAsync(out, x, (size_t)B_ * C_ * H_ * W_ * sizeof(float),
                    cudaMemcpyDeviceToDevice, 0);

    // Pre-split + fragment-pack all weights (2.36MB, L2-resident)
    prepack_kernel<<<(4 * 9 * 8 * 16 * 32 + 255) / 256, 256>>>(
        (const float*)d_in[1], (const float*)d_in[2],
        (const float*)d_in[3], (const float*)d_in[4]);

    const dim3 gridH(2, B_);   // 2 line-tiles of 64 (second partial), full 128 co
    const dim3 gridW(2, B_);   // 2 co-halves, all 36 lines

    // Scan 1: down (axis H, forward), w_d (dir 0)
    for (int h = 1; h < H_; h++)
        mma_step_h<<<gridH, 512, SMEM_H>>>(out, 0, (h - 1) * W_, h * W_);

    // Scan 2: up (axis H, reverse), w_u (dir 1)
    for (int h = H_ - 2; h >= 0; h--)
        mma_step_h<<<gridH, 512, SMEM_H>>>(out, 1, (h + 1) * W_, h * W_);

    // Scan 3: right (axis W, forward), w_r (dir 2)
    for (int w = 1; w < W_; w++)
        mma_step_w<<<gridW, 256, SMEM_W>>>(out, 2, w - 1, w);

    // Scan 4: left (axis W, reverse), w_l (dir 3)
    for (int w = W_ - 2; w >= 0; w--)
        mma_step_w<<<gridW, 256, SMEM_W>>>(out, 3, w + 1, w);
}